// round 9
// baseline (speedup 1.0000x reference)
#include <cuda_runtime.h>
#include <math.h>

// UserCollaborativeFiltering — round 9.
// R8 proved occupancy/MLP are not the limiter (occ 90%, DRAM stuck at 63%):
// the kernel is bound by DRAM *traffic* (175MB, mostly 64B-granularity waste
// on 18KB-strided gathers). Samples sharing time_id t gather from the same
// [U,I] slice and collide on 64B lines (~40% within-row line sharing across
// the ~256 same-t samples). A counting sort by t makes same-t samples
// temporally adjacent so those collisions become L2 hits instead of repeat
// DRAM fetches. Outputs are written to out[original_b]: result identical
// and deterministic regardless of permutation order.

#define JMAX 5          // ceil(142/32)
#define MAX_T 1024      // histogram capacity (T=64 here)
#define PERM_CAP (1<<20)

__device__ int g_hist[MAX_T];    // exclusive-scanned bases (after k_scan)
__device__ int g_cursor[MAX_T];  // scatter cursors
__device__ int g_perm[PERM_CAP];

// Monotone float -> u32 (order-preserving). 0u reserved as "removed".
__device__ __forceinline__ unsigned f2ord(float f) {
    unsigned b = __float_as_uint(f);
    return (b & 0x80000000u) ? ~b : (b | 0x80000000u);
}
__device__ __forceinline__ float ord2f(unsigned o) {
    unsigned b = (o & 0x80000000u) ? (o ^ 0x80000000u) : ~o;
    return __uint_as_float(b);
}

// ---- sort pipeline -------------------------------------------------------

__global__ void k_zero(int T) {
    int i = blockIdx.x * blockDim.x + threadIdx.x;
    if (i < T) { g_hist[i] = 0; g_cursor[i] = 0; }
}

__global__ void k_hist(const int* __restrict__ time_id, int B, int T) {
    __shared__ int sh[MAX_T];
    for (int i = threadIdx.x; i < T; i += blockDim.x) sh[i] = 0;
    __syncthreads();
    int i = blockIdx.x * blockDim.x + threadIdx.x;
    if (i < B) atomicAdd(&sh[time_id[i]], 1);
    __syncthreads();
    for (int i2 = threadIdx.x; i2 < T; i2 += blockDim.x)
        if (sh[i2]) atomicAdd(&g_hist[i2], sh[i2]);
}

__global__ void k_scan(int T) {  // single block, blockDim.x == MAX_T
    __shared__ int s[MAX_T];
    int i = threadIdx.x;
    int v = (i < T) ? g_hist[i] : 0;
    s[i] = v;
    __syncthreads();
    #pragma unroll
    for (int off = 1; off < MAX_T; off <<= 1) {
        int x = (i >= off) ? s[i - off] : 0;
        __syncthreads();
        s[i] += x;
        __syncthreads();
    }
    if (i < T) g_cursor[i] = s[i] - v;  // exclusive prefix
}

__global__ void k_scatter(const int* __restrict__ time_id, int B) {
    int i = blockIdx.x * blockDim.x + threadIdx.x;
    if (i < B) {
        int pos = atomicAdd(&g_cursor[time_id[i]], 1);
        g_perm[pos] = i;
    }
}

// ---- main kernel ---------------------------------------------------------

__global__ void __launch_bounds__(256) ucf_kernel(
    const float* __restrict__ qos,      // [T,U,I]
    const float* __restrict__ user_avg, // [T,U]
    const float* __restrict__ sim,      // [U,U]
    const int*   __restrict__ user_id,
    const int*   __restrict__ item_id,
    const int*   __restrict__ time_id,
    float*       __restrict__ out,
    int B, int U, int I, int use_perm)
{
    const int warp = blockIdx.x * (blockDim.x >> 5) + (threadIdx.x >> 5);
    if (warp >= B) return;
    const int lane = threadIdx.x & 31;
    const int b = use_perm ? g_perm[warp] : warp;

    const int u  = user_id[b];
    const int it = item_id[b];
    const int t  = time_id[b];

    const float* __restrict__ qcol = qos + ((size_t)t * U) * I + it;

    // Phase 1: 5 independent scattered gathers issued first (MLP).
    float q[JMAX];
    #pragma unroll
    for (int j = 0; j < JMAX; j++) {
        const int v = j * 32 + lane;
        q[j] = (v < U) ? __ldg(qcol + (size_t)v * I) : 0.0f;
    }

    // Phase 2: L2-resident rows.
    const float avg_u = __ldg(user_avg + (size_t)t * U + u);
    const float* __restrict__ simrow = sim + (size_t)u * U;
    const float* __restrict__ avgrow = user_avg + (size_t)t * U;

    unsigned o[JMAX];  // ordered masked-sim keys; 0 = removed / pad
    float    dv[JMAX]; // r_vs - avg_v

    #pragma unroll
    for (int j = 0; j < JMAX; j++) {
        const int v = j * 32 + lane;
        const bool ok = v < U;
        float s = ok ? __ldg(simrow + v) : 0.0f;
        float a = ok ? __ldg(avgrow + v) : 0.0f;
        dv[j] = q[j] - a;
        // Reference: sim_m = rated ? sim : 0.0 (zeros stay candidates);
        // only v>=U padding is excluded.
        o[j] = ok ? f2ord((q[j] > 0.0f) ? s : 0.0f) : 0u;
    }

    unsigned lb = 0u; int lj = 0;
    #pragma unroll
    for (int j = 0; j < JMAX; j++)
        if (o[j] > lb) { lb = o[j]; lj = j; }

    float contrib = 0.0f;
    float simsum  = 0.0f;

    // Phase 3: iterative top-10 extraction (redux max + ballot election).
    #pragma unroll
    for (int k = 0; k < 10; k++) {
        const unsigned m   = __reduce_max_sync(0xffffffffu, lb);
        const unsigned bal = __ballot_sync(0xffffffffu, lb == m);
        const int      wl  = __ffs(bal) - 1;  // ties are zero-weight-safe
        simsum += ord2f(m);
        if (lane == wl) {
            const float w = ord2f(m);
            #pragma unroll
            for (int j = 0; j < JMAX; j++)
                if (j == lj) { contrib += w * dv[j]; o[j] = 0u; }
            lb = 0u; lj = 0;
            #pragma unroll
            for (int j = 0; j < JMAX; j++)
                if (o[j] > lb) { lb = o[j]; lj = j; }
        }
    }

    #pragma unroll
    for (int off = 16; off; off >>= 1)
        contrib += __shfl_xor_sync(0xffffffffu, contrib, off);

    if (lane == 0) {
        float p = contrib / (simsum + 1e-8f);
        if (!isfinite(p)) p = 0.0f;  // mirrors jnp.nan_to_num
        out[b] = avg_u + p;
    }
}

extern "C" void kernel_launch(void* const* d_in, const int* in_sizes, int n_in,
                              void* d_out, int out_size)
{
    const float* qos      = (const float*)d_in[0];
    const float* user_avg = (const float*)d_in[1];
    const float* sim      = (const float*)d_in[2];
    const int*   user_id  = (const int*)d_in[3];
    const int*   item_id  = (const int*)d_in[4];
    const int*   time_id  = (const int*)d_in[5];
    float* out = (float*)d_out;

    int U = (int)(sqrt((double)in_sizes[2]) + 0.5);
    int T = in_sizes[1] / U;
    int I = in_sizes[0] / (T * U);
    int B = in_sizes[3];

    const int use_perm = (T <= MAX_T && B <= PERM_CAP) ? 1 : 0;
    if (use_perm) {
        k_zero<<<(T + 255) / 256, 256>>>(T);
        k_hist<<<(B + 255) / 256, 256>>>(time_id, B, T);
        k_scan<<<1, MAX_T>>>(T);
        k_scatter<<<(B + 255) / 256, 256>>>(time_id, B);
    }

    const int threads = 256;  // 8 warps/block, 1 element per warp
    const int wpb = threads / 32;
    const int blocks = (B + wpb - 1) / wpb;
    ucf_kernel<<<blocks, threads>>>(qos, user_avg, sim,
                                    user_id, item_id, time_id,
                                    out, B, U, I, use_perm);
}

// round 10
// speedup vs baseline: 1.1655x; 1.1655x over previous
#include <cuda_runtime.h>
#include <math.h>

// UserCollaborativeFiltering — round 10.
// R9 showed sort-by-t reuse is real but the sort cost (k_scatter 8.4us from
// 256-deep atomic serialization over 64 addresses) ate the win. This round:
//   * 4096-bin key (t*64 | i>>7): scatter contention 256/addr -> ~4/addr,
//     AND exact (t, i-line) sharers become warp-adjacent (L1/L2 hit
//     guaranteed, not timing-dependent). Unique-line model: 149MB -> 98MB
//     of gather traffic.
//   * 3 sort kernels: k_scan also re-zeroes g_hist for the next graph
//     replay (state invariant across calls; globals start zero-initialized).
//   * main kernel identical to R8 minus the min-blocks clamp.

#define JMAX 5          // ceil(142/32)
#define BINS 4096       // t*64 + (i>>7); valid while T<=64 && I<=8192
#define PERM_CAP (1<<20)

__device__ int g_hist[BINS];     // zero at init; k_scan re-zeroes after use
__device__ int g_cursor[BINS];   // exclusive bases, then scatter cursors
__device__ int g_perm[PERM_CAP];

__device__ __forceinline__ int sort_key(int t, int it) {
    return (t << 6) | (it >> 7);
}

// Monotone float -> u32 (order-preserving). 0u reserved as "removed".
__device__ __forceinline__ unsigned f2ord(float f) {
    unsigned b = __float_as_uint(f);
    return (b & 0x80000000u) ? ~b : (b | 0x80000000u);
}
__device__ __forceinline__ float ord2f(unsigned o) {
    unsigned b = (o & 0x80000000u) ? (o ^ 0x80000000u) : ~o;
    return __uint_as_float(b);
}

// ---- sort pipeline (3 kernels, ~1us each) --------------------------------

__global__ void __launch_bounds__(1024) k_hist(
    const int* __restrict__ time_id, const int* __restrict__ item_id, int B)
{
    __shared__ int sh[BINS];
    #pragma unroll
    for (int j = 0; j < BINS / 1024; j++) sh[threadIdx.x + j * 1024] = 0;
    __syncthreads();
    const int i = blockIdx.x * 1024 + threadIdx.x;
    if (i < B) atomicAdd(&sh[sort_key(time_id[i], item_id[i])], 1);
    __syncthreads();
    #pragma unroll
    for (int j = 0; j < BINS / 1024; j++) {
        const int k = threadIdx.x + j * 1024;
        const int c = sh[k];
        if (c) atomicAdd(&g_hist[k], c);
    }
}

__global__ void __launch_bounds__(1024) k_scan()  // single block
{
    const int tid = threadIdx.x;
    const int lane = tid & 31, wid = tid >> 5;
    int4 v = reinterpret_cast<int4*>(g_hist)[tid];  // bins 4t..4t+3
    const int gsum = v.x + v.y + v.z + v.w;

    // warp inclusive scan of group sums
    int inc = gsum;
    #pragma unroll
    for (int off = 1; off < 32; off <<= 1) {
        int n = __shfl_up_sync(0xffffffffu, inc, off);
        if (lane >= off) inc += n;
    }
    __shared__ int wsum[32];
    if (lane == 31) wsum[wid] = inc;
    __syncthreads();
    if (wid == 0) {
        int w = wsum[lane], wi = w;
        #pragma unroll
        for (int off = 1; off < 32; off <<= 1) {
            int n = __shfl_up_sync(0xffffffffu, wi, off);
            if (lane >= off) wi += n;
        }
        wsum[lane] = wi - w;  // exclusive warp prefix
    }
    __syncthreads();
    const int base = wsum[wid] + (inc - gsum);
    int4 c;
    c.x = base;
    c.y = base + v.x;
    c.z = c.y + v.y;
    c.w = c.z + v.z;
    reinterpret_cast<int4*>(g_cursor)[tid] = c;
    reinterpret_cast<int4*>(g_hist)[tid] = make_int4(0, 0, 0, 0);  // next replay
}

__global__ void __launch_bounds__(1024) k_scatter(
    const int* __restrict__ time_id, const int* __restrict__ item_id, int B)
{
    const int i = blockIdx.x * 1024 + threadIdx.x;
    if (i < B) {
        const int pos = atomicAdd(&g_cursor[sort_key(time_id[i], item_id[i])], 1);
        g_perm[pos] = i;
    }
}

// ---- main kernel ---------------------------------------------------------

__global__ void __launch_bounds__(256) ucf_kernel(
    const float* __restrict__ qos,      // [T,U,I]
    const float* __restrict__ user_avg, // [T,U]
    const float* __restrict__ sim,      // [U,U]
    const int*   __restrict__ user_id,
    const int*   __restrict__ item_id,
    const int*   __restrict__ time_id,
    float*       __restrict__ out,
    int B, int U, int I, int use_perm)
{
    const int warp = blockIdx.x * (blockDim.x >> 5) + (threadIdx.x >> 5);
    if (warp >= B) return;
    const int lane = threadIdx.x & 31;
    const int b = use_perm ? __ldg(&g_perm[warp]) : warp;

    const int u  = user_id[b];
    const int it = item_id[b];
    const int t  = time_id[b];

    const float* __restrict__ qcol = qos + ((size_t)t * U) * I + it;

    // Phase 1: 5 independent scattered gathers issued first. With the
    // (t, i-line) sort, warps sharing lines are adjacent -> L1/L2 hits.
    float q[JMAX];
    #pragma unroll
    for (int j = 0; j < JMAX; j++) {
        const int v = j * 32 + lane;
        q[j] = (v < U) ? __ldg(qcol + (size_t)v * I) : 0.0f;
    }

    // Phase 2: L2-resident rows.
    const float avg_u = __ldg(user_avg + (size_t)t * U + u);
    const float* __restrict__ simrow = sim + (size_t)u * U;
    const float* __restrict__ avgrow = user_avg + (size_t)t * U;

    unsigned o[JMAX];  // ordered masked-sim keys; 0 = removed / pad
    float    dv[JMAX]; // r_vs - avg_v

    #pragma unroll
    for (int j = 0; j < JMAX; j++) {
        const int v = j * 32 + lane;
        const bool ok = v < U;
        float s = ok ? __ldg(simrow + v) : 0.0f;
        float a = ok ? __ldg(avgrow + v) : 0.0f;
        dv[j] = q[j] - a;
        // Reference: sim_m = rated ? sim : 0.0 (zeros stay candidates);
        // only v>=U padding is excluded.
        o[j] = ok ? f2ord((q[j] > 0.0f) ? s : 0.0f) : 0u;
    }

    unsigned lb = 0u; int lj = 0;
    #pragma unroll
    for (int j = 0; j < JMAX; j++)
        if (o[j] > lb) { lb = o[j]; lj = j; }

    float contrib = 0.0f;
    float simsum  = 0.0f;

    // Phase 3: iterative top-10 extraction (redux max + ballot election).
    #pragma unroll
    for (int k = 0; k < 10; k++) {
        const unsigned m   = __reduce_max_sync(0xffffffffu, lb);
        const unsigned bal = __ballot_sync(0xffffffffu, lb == m);
        const int      wl  = __ffs(bal) - 1;  // ties are zero-weight-safe
        simsum += ord2f(m);
        if (lane == wl) {
            const float w = ord2f(m);
            #pragma unroll
            for (int j = 0; j < JMAX; j++)
                if (j == lj) { contrib += w * dv[j]; o[j] = 0u; }
            lb = 0u; lj = 0;
            #pragma unroll
            for (int j = 0; j < JMAX; j++)
                if (o[j] > lb) { lb = o[j]; lj = j; }
        }
    }

    #pragma unroll
    for (int off = 16; off; off >>= 1)
        contrib += __shfl_xor_sync(0xffffffffu, contrib, off);

    if (lane == 0) {
        float p = contrib / (simsum + 1e-8f);
        if (!isfinite(p)) p = 0.0f;  // mirrors jnp.nan_to_num
        out[b] = avg_u + p;
    }
}

extern "C" void kernel_launch(void* const* d_in, const int* in_sizes, int n_in,
                              void* d_out, int out_size)
{
    const float* qos      = (const float*)d_in[0];
    const float* user_avg = (const float*)d_in[1];
    const float* sim      = (const float*)d_in[2];
    const int*   user_id  = (const int*)d_in[3];
    const int*   item_id  = (const int*)d_in[4];
    const int*   time_id  = (const int*)d_in[5];
    float* out = (float*)d_out;

    int U = (int)(sqrt((double)in_sizes[2]) + 0.5);
    int T = in_sizes[1] / U;
    int I = in_sizes[0] / (T * U);
    int B = in_sizes[3];

    const int use_perm = (T <= 64 && I <= 8192 && B <= PERM_CAP) ? 1 : 0;
    if (use_perm) {
        const int hb = (B + 1023) / 1024;
        k_hist<<<hb, 1024>>>(time_id, item_id, B);
        k_scan<<<1, 1024>>>();
        k_scatter<<<hb, 1024>>>(time_id, item_id, B);
    }

    const int threads = 256;  // 8 warps/block, 1 element per warp
    const int wpb = threads / 32;
    const int blocks = (B + wpb - 1) / wpb;
    ucf_kernel<<<blocks, threads>>>(qos, user_avg, sim,
                                    user_id, item_id, time_id,
                                    out, B, U, I, use_perm);
}